// round 16
// baseline (speedup 1.0000x reference)
#include <cuda_runtime.h>
#include <cuda_fp16.h>
#include <cstdint>

// Problem constants
#define B_  32
#define S_  512
#define D_  768
#define H_  12
#define HD_ 64
#define SCALE_ 0.125f
// SCALE * log2(e): scores computed directly in log2 domain
#define QSC 0.18033688011112042f

#define M_TOT (B_ * S_)          // 16384
#define QKV_N (3 * D_)           // 2304

// Scratch (device globals — allocation-free)
__device__ __half g_qkvh[(size_t)M_TOT * QKV_N];   // [M, 3D] fp16 QKV (q pre-scaled)
__device__ __half g_attnh[(size_t)M_TOT * D_];     // [M, D] attn out (fp16)
__device__ __half g_xh[(size_t)M_TOT * D_];        // x as fp16
__device__ __half g_qkvwh[(size_t)QKV_N * D_];     // qkv_w as fp16
__device__ __half g_projwh[(size_t)D_ * D_];       // proj_w as fp16

// ---------------------------------------------------------------------------
// Helpers
// ---------------------------------------------------------------------------
__device__ __forceinline__ void mma_f16(float d[4], const uint32_t a[4],
                                        const uint32_t b[2]) {
    asm volatile(
        "mma.sync.aligned.m16n8k16.row.col.f32.f16.f16.f32 "
        "{%0,%1,%2,%3},{%4,%5,%6,%7},{%8,%9},{%0,%1,%2,%3};\n"
        : "+f"(d[0]), "+f"(d[1]), "+f"(d[2]), "+f"(d[3])
        : "r"(a[0]), "r"(a[1]), "r"(a[2]), "r"(a[3]),
          "r"(b[0]), "r"(b[1]));
}

__device__ __forceinline__ void ldsm_x4(uint32_t r[4], uint32_t saddr) {
    asm volatile(
        "ldmatrix.sync.aligned.m8n8.x4.shared.b16 {%0,%1,%2,%3},[%4];"
        : "=r"(r[0]), "=r"(r[1]), "=r"(r[2]), "=r"(r[3]) : "r"(saddr));
}
__device__ __forceinline__ void ldsm_x4_trans(uint32_t r[4], uint32_t saddr) {
    asm volatile(
        "ldmatrix.sync.aligned.m8n8.x4.trans.shared.b16 {%0,%1,%2,%3},[%4];"
        : "=r"(r[0]), "=r"(r[1]), "=r"(r[2]), "=r"(r[3]) : "r"(saddr));
}

__device__ __forceinline__ void cp_async16(uint32_t saddr, const void* gptr) {
    asm volatile("cp.async.cg.shared.global [%0], [%1], 16;"
                 :: "r"(saddr), "l"(gptr));
}
__device__ __forceinline__ void cp_commit() {
    asm volatile("cp.async.commit_group;");
}
template <int N>
__device__ __forceinline__ void cp_wait() {
    asm volatile("cp.async.wait_group %0;" :: "n"(N));
}

// 2^t on the FMA pipe only.
__device__ __forceinline__ float exp2_poly(float t) {
    float g  = t + 12582912.0f;
    int   j  = __float_as_int(g);
    float nf = g - 12582912.0f;
    float f  = t - nf;
    float p  = 0.0096181f;
    p = fmaf(p, f, 0.0555041f);
    p = fmaf(p, f, 0.2402265f);
    p = fmaf(p, f, 0.6931472f);
    p = fmaf(p, f, 1.0f);
    int n = j - 0x4B400000;
    return __int_as_float(__float_as_int(p) + (n << 23));
}

// ---------------------------------------------------------------------------
// Elementwise f32 -> fp16 (rn) pre-convert pass. 8 elems/iter.
// ---------------------------------------------------------------------------
__global__ void cvt_f16_kernel(const float* __restrict__ in,
                               __half* __restrict__ out, int n8)
{
    int i = blockIdx.x * blockDim.x + threadIdx.x;
    int step = gridDim.x * blockDim.x;
    for (; i < n8; i += step) {
        float4 v0 = *(const float4*)(in + (size_t)i * 8);
        float4 v1 = *(const float4*)(in + (size_t)i * 8 + 4);
        __half2 h0 = __floats2half2_rn(v0.x, v0.y);
        __half2 h1 = __floats2half2_rn(v0.z, v0.w);
        __half2 h2 = __floats2half2_rn(v1.x, v1.y);
        __half2 h3 = __floats2half2_rn(v1.z, v1.w);
        uint4 o;
        o.x = *(uint32_t*)&h0; o.y = *(uint32_t*)&h1;
        o.z = *(uint32_t*)&h2; o.w = *(uint32_t*)&h3;
        *(uint4*)(out + (size_t)i * 8) = o;
    }
}

// ---------------------------------------------------------------------------
// FP16 tensor-core GEMM: 4-stage cp.async pipeline + ldmatrix feed.
// 128 threads = 4 warps (2x2), warp tile 64x64 (4:1 MMA:LDSM issue ratio).
// C[M,N] = A[M,K] @ B[N,K]^T + bias[N]
// BM=BN=128, BK=32 halfs.
// ---------------------------------------------------------------------------
#define BM 128
#define BN 128
#define BKH 32
#define LDW 20
#define STAGES 4
#define A_WORDS (BM * LDW)
#define STG_WORDS ((BM + BN) * LDW)
#define GEMM_SMEM_BYTES (STAGES * STG_WORDS * 4)   // 81920

template <bool HOUT>
__global__ __launch_bounds__(128, 2) void gemm_f16_kernel(
    const __half* __restrict__ A, const __half* __restrict__ Bw,
    const float* __restrict__ bias, void* __restrict__ Cv,
    int M, int N, int K)
{
    extern __shared__ uint32_t gsm[];

    const int tid  = threadIdx.x;
    const int lane = tid & 31;
    const int warp = tid >> 5;        // 0..3
    const int wm   = warp >> 1;       // 0..1 : 64-row half
    const int wn   = warp & 1;        // 0..1 : 64-col half
    const int m0   = blockIdx.y * BM;
    const int n0   = blockIdx.x * BN;

    // loader: 128 threads cover 128 rows x 4 chunks per matrix in 4 iters
    const int lrow = tid >> 2;        // 0..31
    const int lq   = tid & 3;

    const __half* Aptr = A  + (size_t)(m0 + lrow) * K + lq * 8;
    const __half* Bptr = Bw + (size_t)(n0 + lrow) * K + lq * 8;

    const uint32_t smem_base = (uint32_t)__cvta_generic_to_shared(gsm);
    uint32_t a_off[4], b_off[4];
    #pragma unroll
    for (int i = 0; i < 4; i++) {
        a_off[i] = ((lrow + 32 * i) * LDW + lq * 4) * 4;
        b_off[i] = (A_WORDS + (lrow + 32 * i) * LDW + lq * 4) * 4;
    }

    // ldmatrix lane addressing
    const int a_lr = (lane & 7) + ((lane >> 3) & 1) * 8;
    const int a_lk = ((lane >> 4) & 1) * 4;
    const int b_lr = (lane & 7) + ((lane >> 4) & 1) * 8;
    const int b_lk = ((lane >> 3) & 1) * 4;

    const int nk = K / BKH;

    float acc[4][8][4];
    #pragma unroll
    for (int mi = 0; mi < 4; mi++)
        #pragma unroll
        for (int ni = 0; ni < 8; ni++)
            #pragma unroll
            for (int r = 0; r < 4; r++) acc[mi][ni][r] = 0.0f;

    #pragma unroll
    for (int s = 0; s < STAGES - 1; s++) {
        uint32_t sb = smem_base + s * STG_WORDS * 4;
        const __half* Ak = Aptr + (size_t)s * BKH;
        const __half* Bk = Bptr + (size_t)s * BKH;
        #pragma unroll
        for (int i = 0; i < 4; i++) {
            cp_async16(sb + a_off[i], Ak + (size_t)(32 * i) * K);
            cp_async16(sb + b_off[i], Bk + (size_t)(32 * i) * K);
        }
        cp_commit();
    }

    const int qr = lane >> 2;
    const int qc = lane & 3;

    for (int kt = 0; kt < nk; kt++) {
        cp_wait<STAGES - 2>();
        __syncthreads();

        if (kt + STAGES - 1 < nk) {
            int s = (kt + STAGES - 1) & (STAGES - 1);
            uint32_t sb = smem_base + s * STG_WORDS * 4;
            const __half* Ak = Aptr + (size_t)(kt + STAGES - 1) * BKH;
            const __half* Bk = Bptr + (size_t)(kt + STAGES - 1) * BKH;
            #pragma unroll
            for (int i = 0; i < 4; i++) {
                cp_async16(sb + a_off[i], Ak + (size_t)(32 * i) * K);
                cp_async16(sb + b_off[i], Bk + (size_t)(32 * i) * K);
            }
        }
        cp_commit();

        const uint32_t stg = smem_base + (kt & (STAGES - 1)) * STG_WORDS * 4;

        #pragma unroll
        for (int ks = 0; ks < 2; ks++) {
            const int kb = ks * 8;
            uint32_t afr[4][4];
            #pragma unroll
            for (int mi = 0; mi < 4; mi++)
                ldsm_x4(afr[mi],
                        stg + ((wm * 64 + mi * 16 + a_lr) * LDW + kb + a_lk) * 4);
            uint32_t bfr[4][4];
            #pragma unroll
            for (int p = 0; p < 4; p++)
                ldsm_x4(bfr[p],
                        stg + (A_WORDS + (wn * 64 + p * 16 + b_lr) * LDW + kb + b_lk) * 4);
            #pragma unroll
            for (int mi = 0; mi < 4; mi++)
                #pragma unroll
                for (int p = 0; p < 4; p++) {
                    mma_f16(acc[mi][2 * p],     afr[mi], &bfr[p][0]);
                    mma_f16(acc[mi][2 * p + 1], afr[mi], &bfr[p][2]);
                }
        }
    }

    // Epilogue
    #pragma unroll
    for (int ni = 0; ni < 8; ni++) {
        int col = n0 + wn * 64 + ni * 8 + qc * 2;
        float2 bv = *(const float2*)(bias + col);
        float scl = 1.0f;
        if (HOUT && col < D_) scl = QSC;   // q-block pre-scale (log2 domain)
        #pragma unroll
        for (int mi = 0; mi < 4; mi++) {
            int row = m0 + wm * 64 + mi * 16 + qr;
            float o00 = (acc[mi][ni][0] + bv.x) * scl;
            float o01 = (acc[mi][ni][1] + bv.y) * scl;
            float o10 = (acc[mi][ni][2] + bv.x) * scl;
            float o11 = (acc[mi][ni][3] + bv.y) * scl;
            if (HOUT) {
                __half* Ch = (__half*)Cv;
                *(__half2*)(Ch + (size_t)row * N + col) =
                    __floats2half2_rn(o00, o01);
                *(__half2*)(Ch + (size_t)(row + 8) * N + col) =
                    __floats2half2_rn(o10, o11);
            } else {
                float* Cf = (float*)Cv;
                *(float2*)(Cf + (size_t)row * N + col) = make_float2(o00, o01);
                *(float2*)(Cf + (size_t)(row + 8) * N + col) = make_float2(o10, o11);
            }
        }
    }
}

// ---------------------------------------------------------------------------
// FP16 flash attention: 128-row Q tiles, 3-stage cp.async K/V ring,
// ldmatrix fragment feed, trans-ldmatrix V.  (unchanged from round 15)
// ---------------------------------------------------------------------------
#define AST 36
#define Q_WORDS (128 * AST)
#define KV_STG_WORDS (128 * AST)
#define AT_WORDS (2 * Q_WORDS + 3 * KV_STG_WORDS)
#define AT_BYTES (AT_WORDS * 4)        // 92160

__global__ __launch_bounds__(256) void attn_f16_kernel(
    const __half* __restrict__ qkv, __half* __restrict__ out)
{
    const int bid = blockIdx.x;
    const int qt  = bid & 3;
    const int h   = (bid >> 2) % H_;
    const int b   = bid / (H_ * 4);

    const int tid  = threadIdx.x;
    const int lane = tid & 31;
    const int warp = tid >> 5;
    const int qr   = lane >> 2;
    const int qc   = lane & 3;
    const int R    = warp * 16;

    extern __shared__ uint32_t smu[];
    uint32_t* Ps = smu + Q_WORDS;

    const uint32_t sb = (uint32_t)__cvta_generic_to_shared(smu);
    const uint32_t Qb = sb;
    const uint32_t Pb = sb + Q_WORDS * 4;
    const uint32_t KVb = sb + 2 * Q_WORDS * 4;

    const int a_lr = (lane & 7) + ((lane >> 3) & 1) * 8;
    const int a_lk = ((lane >> 4) & 1) * 4;
    const int b_lr = (lane & 7) + ((lane >> 4) & 1) * 8;
    const int b_lk = ((lane >> 3) & 1) * 4;
    const int v_lk = (lane & 7) + ((lane >> 3) & 1) * 8;
    const int v_ld = ((lane >> 4) & 1) * 4;

    const int krow0 = tid >> 3;
    const int krow1 = krow0 + 32;
    const int kc    = tid & 7;

    const __half* kv_base = qkv + (size_t)(b * S_) * QKV_N + D_ + h * HD_;

    #pragma unroll
    for (int s = 0; s < 2; s++) {
        uint32_t stg = KVb + s * KV_STG_WORDS * 4;
        const __half* kb = kv_base + (size_t)(s * 64) * QKV_N;
        cp_async16(stg + (krow0 * AST + kc * 4) * 4, kb + (size_t)krow0 * QKV_N + kc * 8);
        cp_async16(stg + (krow1 * AST + kc * 4) * 4, kb + (size_t)krow1 * QKV_N + kc * 8);
        cp_async16(stg + ((64 + krow0) * AST + kc * 4) * 4, kb + (size_t)krow0 * QKV_N + D_ + kc * 8);
        cp_async16(stg + ((64 + krow1) * AST + kc * 4) * 4, kb + (size_t)krow1 * QKV_N + D_ + kc * 8);
        cp_commit();
    }

    const __half* qbase = qkv + (size_t)(b * S_ + qt * 128) * QKV_N + h * HD_;
    for (int t = tid; t < 1024; t += 256) {
        int r = t >> 3;
        int c = t & 7;
        uint4 v = *(const uint4*)(qbase + (size_t)r * QKV_N + c * 8);
        *(uint4*)&smu[r * AST + c * 4] = v;
    }

    float m1 = -1e30f, m2 = -1e30f, l1 = 0.0f, l2 = 0.0f;
    float o[8][4];
    #pragma unroll
    for (int nt = 0; nt < 8; nt++)
        #pragma unroll
        for (int r = 0; r < 4; r++) o[nt][r] = 0.0f;

    int stage = 0;
    for (int kt = 0; kt < 8; kt++) {
        cp_wait<1>();
        __syncthreads();

        if (kt + 2 < 8) {
            int s2 = stage + 2; if (s2 >= 3) s2 -= 3;
            uint32_t stg = KVb + s2 * KV_STG_WORDS * 4;
            const __half* kb = kv_base + (size_t)((kt + 2) * 64) * QKV_N;
            cp_async16(stg + (krow0 * AST + kc * 4) * 4, kb + (size_t)krow0 * QKV_N + kc * 8);
            cp_async16(stg + (krow1 * AST + kc * 4) * 4, kb + (size_t)krow1 * QKV_N + kc * 8);
            cp_async16(stg + ((64 + krow0) * AST + kc * 4) * 4, kb + (size_t)krow0 * QKV_N + D_ + kc * 8);
            cp_async16(stg + ((64 + krow1) * AST + kc * 4) * 4, kb + (size_t)krow1 * QKV_N + D_ + kc * 8);
        }
        cp_commit();

        const uint32_t Kb = KVb + stage * KV_STG_WORDS * 4;
        const uint32_t Vb = Kb + 64 * AST * 4;

        float s[8][4];
        #pragma unroll
        for (int nt = 0; nt < 8; nt++)
            #pragma unroll
            for (int r = 0; r < 4; r++) s[nt][r] = 0.0f;

        #pragma unroll
        for (int ks = 0; ks < 4; ks++) {
            const int kb = ks * 8;
            uint32_t a[4];
            ldsm_x4(a, Qb + ((R + a_lr) * AST + kb + a_lk) * 4);
            #pragma unroll
            for (int p = 0; p < 4; p++) {
                uint32_t bb[4];
                ldsm_x4(bb, Kb + ((p * 16 + b_lr) * AST + kb + b_lk) * 4);
                mma_f16(s[2 * p],     a, &bb[0]);
                mma_f16(s[2 * p + 1], a, &bb[2]);
            }
        }

        float mx1 = -1e30f, mx2 = -1e30f;
        #pragma unroll
        for (int nt = 0; nt < 8; nt++) {
            mx1 = fmaxf(mx1, fmaxf(s[nt][0], s[nt][1]));
            mx2 = fmaxf(mx2, fmaxf(s[nt][2], s[nt][3]));
        }
        mx1 = fmaxf(mx1, __shfl_xor_sync(0xffffffffu, mx1, 1));
        mx1 = fmaxf(mx1, __shfl_xor_sync(0xffffffffu, mx1, 2));
        mx2 = fmaxf(mx2, __shfl_xor_sync(0xffffffffu, mx2, 1));
        mx2 = fmaxf(mx2, __shfl_xor_sync(0xffffffffu, mx2, 2));

        float mn1 = fmaxf(m1, mx1);
        float mn2 = fmaxf(m2, mx2);
        float c1 = exp2f(m1 - mn1);
        float c2 = exp2f(m2 - mn2);
        m1 = mn1; m2 = mn2;

        float rs1 = 0.0f, rs2 = 0.0f;
        #pragma unroll
        for (int nt = 0; nt < 8; nt++) {
            s[nt][0] = exp2_poly(s[nt][0] - mn1);
            s[nt][1] = exp2_poly(s[nt][1] - mn1);
            s[nt][2] = exp2_poly(s[nt][2] - mn2);
            s[nt][3] = exp2_poly(s[nt][3] - mn2);
            rs1 += s[nt][0] + s[nt][1];
            rs2 += s[nt][2] + s[nt][3];
        }
        rs1 += __shfl_xor_sync(0xffffffffu, rs1, 1);
        rs1 += __shfl_xor_sync(0xffffffffu, rs1, 2);
        rs2 += __shfl_xor_sync(0xffffffffu, rs2, 1);
        rs2 += __shfl_xor_sync(0xffffffffu, rs2, 2);
        l1 = l1 * c1 + rs1;
        l2 = l2 * c2 + rs2;

        #pragma unroll
        for (int nt = 0; nt < 8; nt++) {
            o[nt][0] *= c1; o[nt][1] *= c1;
            o[nt][2] *= c2; o[nt][3] *= c2;
        }

        #pragma unroll
        for (int nt = 0; nt < 8; nt++) {
            __half2 p0 = __floats2half2_rn(s[nt][0], s[nt][1]);
            __half2 p1 = __floats2half2_rn(s[nt][2], s[nt][3]);
            Ps[(R + qr) * AST + nt * 4 + qc]     = *(uint32_t*)&p0;
            Ps[(R + qr + 8) * AST + nt * 4 + qc] = *(uint32_t*)&p1;
        }
        __syncwarp();

        #pragma unroll
        for (int ks = 0; ks < 4; ks++) {
            const int kb = ks * 8;
            uint32_t a[4];
            ldsm_x4(a, Pb + ((R + a_lr) * AST + kb + a_lk) * 4);
            #pragma unroll
            for (int p = 0; p < 4; p++) {
                uint32_t bb[4];
                ldsm_x4_trans(bb, Vb + ((ks * 16 + v_lk) * AST + p * 8 + v_ld) * 4);
                mma_f16(o[2 * p],     a, &bb[0]);
                mma_f16(o[2 * p + 1], a, &bb[2]);
            }
        }
        __syncwarp();

        if (++stage == 3) stage = 0;
    }

    float i1 = 1.0f / l1;
    float i2 = 1.0f / l2;
    __half* ob = out + (size_t)(b * S_ + qt * 128) * D_ + h * HD_;
    #pragma unroll
    for (int nt = 0; nt < 8; nt++) {
        int col = nt * 8 + 2 * qc;
        __half2 w0 = __floats2half2_rn(o[nt][0] * i1, o[nt][1] * i1);
        __half2 w1 = __floats2half2_rn(o[nt][2] * i2, o[nt][3] * i2);
        *(__half2*)(ob + (size_t)(R + qr) * D_ + col)     = w0;
        *(__half2*)(ob + (size_t)(R + qr + 8) * D_ + col) = w1;
    }
}

// ---------------------------------------------------------------------------
// Launch
// ---------------------------------------------------------------------------
extern "C" void kernel_launch(void* const* d_in, const int* in_sizes, int n_in,
                              void* d_out, int out_size)
{
    const float* x      = (const float*)d_in[0];
    const float* qkv_w  = (const float*)d_in[1];
    const float* qkv_b  = (const float*)d_in[2];
    const float* proj_w = (const float*)d_in[3];
    const float* proj_b = (const float*)d_in[4];
    float* out = (float*)d_out;

    void *qkvh_p, *attnh_p, *xh_p, *qkvwh_p, *projwh_p;
    cudaGetSymbolAddress(&qkvh_p, g_qkvh);
    cudaGetSymbolAddress(&attnh_p, g_attnh);
    cudaGetSymbolAddress(&xh_p, g_xh);
    cudaGetSymbolAddress(&qkvwh_p, g_qkvwh);
    cudaGetSymbolAddress(&projwh_p, g_projwh);
    __half* qkvh_s   = (__half*)qkvh_p;
    __half* attnh_s  = (__half*)attnh_p;
    __half* xh_s     = (__half*)xh_p;
    __half* qkvwh_s  = (__half*)qkvwh_p;
    __half* projwh_s = (__half*)projwh_p;

    cudaFuncSetAttribute(gemm_f16_kernel<true>,
                         cudaFuncAttributeMaxDynamicSharedMemorySize,
                         GEMM_SMEM_BYTES);
    cudaFuncSetAttribute(gemm_f16_kernel<false>,
                         cudaFuncAttributeMaxDynamicSharedMemorySize,
                         GEMM_SMEM_BYTES);
    cudaFuncSetAttribute(attn_f16_kernel,
                         cudaFuncAttributeMaxDynamicSharedMemorySize,
                         AT_BYTES);

    // 0) Pre-convert inputs to fp16 (rn)
    cvt_f16_kernel<<<1024, 256>>>(x, xh_s, M_TOT * D_ / 8);
    cvt_f16_kernel<<<512, 256>>>(qkv_w, qkvwh_s, QKV_N * D_ / 8);
    cvt_f16_kernel<<<256, 256>>>(proj_w, projwh_s, D_ * D_ / 8);

    // 1) QKV projection -> fp16 qkv (q cols pre-scaled by QSC)
    gemm_f16_kernel<true><<<dim3(QKV_N / BN, M_TOT / BM), 128, GEMM_SMEM_BYTES>>>(
        xh_s, qkvwh_s, qkv_b, qkvh_s, M_TOT, QKV_N, D_);

    // 2) Flash attention (128-row Q tiles, cp.async K/V ring)
    attn_f16_kernel<<<B_ * H_ * (S_ / 128), 256, AT_BYTES>>>(qkvh_s, attnh_s);

    // 3) Output projection -> f32 out
    gemm_f16_kernel<false><<<dim3(D_ / BN, M_TOT / BM), 128, GEMM_SMEM_BYTES>>>(
        attnh_s, projwh_s, proj_b, out, M_TOT, D_, D_);
}

// round 17
// speedup vs baseline: 1.4375x; 1.4375x over previous
#include <cuda_runtime.h>
#include <cuda_fp16.h>
#include <cstdint>

// Problem constants
#define B_  32
#define S_  512
#define D_  768
#define H_  12
#define HD_ 64
#define SCALE_ 0.125f
// SCALE * log2(e): scores computed directly in log2 domain
#define QSC 0.18033688011112042f

#define M_TOT (B_ * S_)          // 16384
#define QKV_N (3 * D_)           // 2304

// Scratch (device globals — allocation-free)
__device__ __half g_qkvh[(size_t)M_TOT * QKV_N];   // [M, 3D] fp16 QKV (q pre-scaled)
__device__ __half g_attnh[(size_t)M_TOT * D_];     // [M, D] attn out (fp16)
__device__ __half g_xh[(size_t)M_TOT * D_];        // x as fp16
__device__ __half g_qkvwh[(size_t)QKV_N * D_];     // qkv_w as fp16
__device__ __half g_projwh[(size_t)D_ * D_];       // proj_w as fp16

// ---------------------------------------------------------------------------
// Helpers
// ---------------------------------------------------------------------------
__device__ __forceinline__ void mma_f16(float d[4], const uint32_t a[4],
                                        const uint32_t b[2]) {
    asm volatile(
        "mma.sync.aligned.m16n8k16.row.col.f32.f16.f16.f32 "
        "{%0,%1,%2,%3},{%4,%5,%6,%7},{%8,%9},{%0,%1,%2,%3};\n"
        : "+f"(d[0]), "+f"(d[1]), "+f"(d[2]), "+f"(d[3])
        : "r"(a[0]), "r"(a[1]), "r"(a[2]), "r"(a[3]),
          "r"(b[0]), "r"(b[1]));
}

__device__ __forceinline__ void ldsm_x4(uint32_t r[4], uint32_t saddr) {
    asm volatile(
        "ldmatrix.sync.aligned.m8n8.x4.shared.b16 {%0,%1,%2,%3},[%4];"
        : "=r"(r[0]), "=r"(r[1]), "=r"(r[2]), "=r"(r[3]) : "r"(saddr));
}
__device__ __forceinline__ void ldsm_x4_trans(uint32_t r[4], uint32_t saddr) {
    asm volatile(
        "ldmatrix.sync.aligned.m8n8.x4.trans.shared.b16 {%0,%1,%2,%3},[%4];"
        : "=r"(r[0]), "=r"(r[1]), "=r"(r[2]), "=r"(r[3]) : "r"(saddr));
}

__device__ __forceinline__ void cp_async16(uint32_t saddr, const void* gptr) {
    asm volatile("cp.async.cg.shared.global [%0], [%1], 16;"
                 :: "r"(saddr), "l"(gptr));
}
__device__ __forceinline__ void cp_commit() {
    asm volatile("cp.async.commit_group;");
}
template <int N>
__device__ __forceinline__ void cp_wait() {
    asm volatile("cp.async.wait_group %0;" :: "n"(N));
}

// 2^t on the FMA pipe only.
__device__ __forceinline__ float exp2_poly(float t) {
    float g  = t + 12582912.0f;
    int   j  = __float_as_int(g);
    float nf = g - 12582912.0f;
    float f  = t - nf;
    float p  = 0.0096181f;
    p = fmaf(p, f, 0.0555041f);
    p = fmaf(p, f, 0.2402265f);
    p = fmaf(p, f, 0.6931472f);
    p = fmaf(p, f, 1.0f);
    int n = j - 0x4B400000;
    return __int_as_float(__float_as_int(p) + (n << 23));
}

// ---------------------------------------------------------------------------
// Elementwise f32 -> fp16 (rn) pre-convert pass. 8 elems/iter.
// ---------------------------------------------------------------------------
__global__ void cvt_f16_kernel(const float* __restrict__ in,
                               __half* __restrict__ out, int n8)
{
    int i = blockIdx.x * blockDim.x + threadIdx.x;
    int step = gridDim.x * blockDim.x;
    for (; i < n8; i += step) {
        float4 v0 = *(const float4*)(in + (size_t)i * 8);
        float4 v1 = *(const float4*)(in + (size_t)i * 8 + 4);
        __half2 h0 = __floats2half2_rn(v0.x, v0.y);
        __half2 h1 = __floats2half2_rn(v0.z, v0.w);
        __half2 h2 = __floats2half2_rn(v1.x, v1.y);
        __half2 h3 = __floats2half2_rn(v1.z, v1.w);
        uint4 o;
        o.x = *(uint32_t*)&h0; o.y = *(uint32_t*)&h1;
        o.z = *(uint32_t*)&h2; o.w = *(uint32_t*)&h3;
        *(uint4*)(out + (size_t)i * 8) = o;
    }
}

// ---------------------------------------------------------------------------
// FP16 tensor-core GEMM: 4-stage cp.async pipeline + ldmatrix fragment feed.
// C[M,N] = A[M,K] @ B[N,K]^T + bias[N]
// BM=BN=128, BK=32 halfs. 256 threads = 8 warps (2x4), warp tile 64x32.
// (round-15 configuration — best measured)
// ---------------------------------------------------------------------------
#define BM 128
#define BN 128
#define BKH 32
#define LDW 20
#define STAGES 4
#define A_WORDS (BM * LDW)
#define STG_WORDS ((BM + BN) * LDW)
#define GEMM_SMEM_BYTES (STAGES * STG_WORDS * 4)   // 81920

template <bool HOUT>
__global__ __launch_bounds__(256) void gemm_f16_kernel(
    const __half* __restrict__ A, const __half* __restrict__ Bw,
    const float* __restrict__ bias, void* __restrict__ Cv,
    int M, int N, int K)
{
    extern __shared__ uint32_t gsm[];

    const int tid  = threadIdx.x;
    const int lane = tid & 31;
    const int warp = tid >> 5;
    const int wm   = warp >> 2;
    const int wn   = warp & 3;
    const int m0   = blockIdx.y * BM;
    const int n0   = blockIdx.x * BN;

    const int lrow = tid >> 2;
    const int lq   = tid & 3;

    const __half* Aptr = A  + (size_t)(m0 + lrow) * K + lq * 8;
    const __half* Bptr = Bw + (size_t)(n0 + lrow) * K + lq * 8;

    const uint32_t smem_base = (uint32_t)__cvta_generic_to_shared(gsm);
    const uint32_t a_off0 = ((lrow)      * LDW + lq * 4) * 4;
    const uint32_t a_off1 = ((lrow + 64) * LDW + lq * 4) * 4;
    const uint32_t b_off0 = (A_WORDS + (lrow)      * LDW + lq * 4) * 4;
    const uint32_t b_off1 = (A_WORDS + (lrow + 64) * LDW + lq * 4) * 4;

    // ldmatrix lane addressing
    const int a_lr = (lane & 7) + ((lane >> 3) & 1) * 8;
    const int a_lk = ((lane >> 4) & 1) * 4;
    const int b_lr = (lane & 7) + ((lane >> 4) & 1) * 8;
    const int b_lk = ((lane >> 3) & 1) * 4;

    const int nk = K / BKH;

    float acc[4][4][4];
    #pragma unroll
    for (int mi = 0; mi < 4; mi++)
        #pragma unroll
        for (int ni = 0; ni < 4; ni++)
            #pragma unroll
            for (int r = 0; r < 4; r++) acc[mi][ni][r] = 0.0f;

    #pragma unroll
    for (int s = 0; s < STAGES - 1; s++) {
        uint32_t sb = smem_base + s * STG_WORDS * 4;
        const __half* Ak = Aptr + (size_t)s * BKH;
        const __half* Bk = Bptr + (size_t)s * BKH;
        cp_async16(sb + a_off0, Ak);
        cp_async16(sb + a_off1, Ak + (size_t)64 * K);
        cp_async16(sb + b_off0, Bk);
        cp_async16(sb + b_off1, Bk + (size_t)64 * K);
        cp_commit();
    }

    const int qr = lane >> 2;
    const int qc = lane & 3;

    for (int kt = 0; kt < nk; kt++) {
        cp_wait<STAGES - 2>();
        __syncthreads();

        if (kt + STAGES - 1 < nk) {
            int s = (kt + STAGES - 1) & (STAGES - 1);
            uint32_t sb = smem_base + s * STG_WORDS * 4;
            const __half* Ak = Aptr + (size_t)(kt + STAGES - 1) * BKH;
            const __half* Bk = Bptr + (size_t)(kt + STAGES - 1) * BKH;
            cp_async16(sb + a_off0, Ak);
            cp_async16(sb + a_off1, Ak + (size_t)64 * K);
            cp_async16(sb + b_off0, Bk);
            cp_async16(sb + b_off1, Bk + (size_t)64 * K);
        }
        cp_commit();

        const uint32_t stg = smem_base + (kt & (STAGES - 1)) * STG_WORDS * 4;

        #pragma unroll
        for (int ks = 0; ks < 2; ks++) {
            const int kb = ks * 8;
            uint32_t afr[4][4];
            #pragma unroll
            for (int mi = 0; mi < 4; mi++)
                ldsm_x4(afr[mi],
                        stg + ((wm * 64 + mi * 16 + a_lr) * LDW + kb + a_lk) * 4);
            uint32_t bfr[2][4];
            #pragma unroll
            for (int p = 0; p < 2; p++)
                ldsm_x4(bfr[p],
                        stg + (A_WORDS + (wn * 32 + p * 16 + b_lr) * LDW + kb + b_lk) * 4);
            #pragma unroll
            for (int mi = 0; mi < 4; mi++)
                #pragma unroll
                for (int p = 0; p < 2; p++) {
                    mma_f16(acc[mi][2 * p],     afr[mi], &bfr[p][0]);
                    mma_f16(acc[mi][2 * p + 1], afr[mi], &bfr[p][2]);
                }
        }
    }

    // Epilogue
    #pragma unroll
    for (int ni = 0; ni < 4; ni++) {
        int col = n0 + wn * 32 + ni * 8 + qc * 2;
        float2 bv = *(const float2*)(bias + col);
        float scl = 1.0f;
        if (HOUT && col < D_) scl = QSC;   // q-block pre-scale (log2 domain)
        #pragma unroll
        for (int mi = 0; mi < 4; mi++) {
            int row = m0 + wm * 64 + mi * 16 + qr;
            float o00 = (acc[mi][ni][0] + bv.x) * scl;
            float o01 = (acc[mi][ni][1] + bv.y) * scl;
            float o10 = (acc[mi][ni][2] + bv.x) * scl;
            float o11 = (acc[mi][ni][3] + bv.y) * scl;
            if (HOUT) {
                __half* Ch = (__half*)Cv;
                *(__half2*)(Ch + (size_t)row * N + col) =
                    __floats2half2_rn(o00, o01);
                *(__half2*)(Ch + (size_t)(row + 8) * N + col) =
                    __floats2half2_rn(o10, o11);
            } else {
                float* Cf = (float*)Cv;
                *(float2*)(Cf + (size_t)row * N + col) = make_float2(o00, o01);
                *(float2*)(Cf + (size_t)(row + 8) * N + col) = make_float2(o10, o11);
            }
        }
    }
}

// ---------------------------------------------------------------------------
// FP16 flash attention: 128-row Q tiles, 3-stage cp.async K/V ring,
// ldmatrix fragment feed, trans-ldmatrix V.
// __launch_bounds__(256, 2): cap regs at 128 to force 2 CTAs/SM residency.
// ---------------------------------------------------------------------------
#define AST 36
#define Q_WORDS (128 * AST)
#define KV_STG_WORDS (128 * AST)
#define AT_WORDS (2 * Q_WORDS + 3 * KV_STG_WORDS)
#define AT_BYTES (AT_WORDS * 4)        // 92160

__global__ __launch_bounds__(256, 2) void attn_f16_kernel(
    const __half* __restrict__ qkv, __half* __restrict__ out)
{
    const int bid = blockIdx.x;
    const int qt  = bid & 3;
    const int h   = (bid >> 2) % H_;
    const int b   = bid / (H_ * 4);

    const int tid  = threadIdx.x;
    const int lane = tid & 31;
    const int warp = tid >> 5;
    const int qr   = lane >> 2;
    const int qc   = lane & 3;
    const int R    = warp * 16;

    extern __shared__ uint32_t smu[];
    uint32_t* Ps = smu + Q_WORDS;

    const uint32_t sb = (uint32_t)__cvta_generic_to_shared(smu);
    const uint32_t Qb = sb;
    const uint32_t Pb = sb + Q_WORDS * 4;
    const uint32_t KVb = sb + 2 * Q_WORDS * 4;

    const int a_lr = (lane & 7) + ((lane >> 3) & 1) * 8;
    const int a_lk = ((lane >> 4) & 1) * 4;
    const int b_lr = (lane & 7) + ((lane >> 4) & 1) * 8;
    const int b_lk = ((lane >> 3) & 1) * 4;
    const int v_lk = (lane & 7) + ((lane >> 3) & 1) * 8;
    const int v_ld = ((lane >> 4) & 1) * 4;

    const int krow0 = tid >> 3;
    const int krow1 = krow0 + 32;
    const int kc    = tid & 7;

    const __half* kv_base = qkv + (size_t)(b * S_) * QKV_N + D_ + h * HD_;

    #pragma unroll
    for (int s = 0; s < 2; s++) {
        uint32_t stg = KVb + s * KV_STG_WORDS * 4;
        const __half* kb = kv_base + (size_t)(s * 64) * QKV_N;
        cp_async16(stg + (krow0 * AST + kc * 4) * 4, kb + (size_t)krow0 * QKV_N + kc * 8);
        cp_async16(stg + (krow1 * AST + kc * 4) * 4, kb + (size_t)krow1 * QKV_N + kc * 8);
        cp_async16(stg + ((64 + krow0) * AST + kc * 4) * 4, kb + (size_t)krow0 * QKV_N + D_ + kc * 8);
        cp_async16(stg + ((64 + krow1) * AST + kc * 4) * 4, kb + (size_t)krow1 * QKV_N + D_ + kc * 8);
        cp_commit();
    }

    const __half* qbase = qkv + (size_t)(b * S_ + qt * 128) * QKV_N + h * HD_;
    for (int t = tid; t < 1024; t += 256) {
        int r = t >> 3;
        int c = t & 7;
        uint4 v = *(const uint4*)(qbase + (size_t)r * QKV_N + c * 8);
        *(uint4*)&smu[r * AST + c * 4] = v;
    }

    float m1 = -1e30f, m2 = -1e30f, l1 = 0.0f, l2 = 0.0f;
    float o[8][4];
    #pragma unroll
    for (int nt = 0; nt < 8; nt++)
        #pragma unroll
        for (int r = 0; r < 4; r++) o[nt][r] = 0.0f;

    int stage = 0;
    for (int kt = 0; kt < 8; kt++) {
        cp_wait<1>();
        __syncthreads();

        if (kt + 2 < 8) {
            int s2 = stage + 2; if (s2 >= 3) s2 -= 3;
            uint32_t stg = KVb + s2 * KV_STG_WORDS * 4;
            const __half* kb = kv_base + (size_t)((kt + 2) * 64) * QKV_N;
            cp_async16(stg + (krow0 * AST + kc * 4) * 4, kb + (size_t)krow0 * QKV_N + kc * 8);
            cp_async16(stg + (krow1 * AST + kc * 4) * 4, kb + (size_t)krow1 * QKV_N + kc * 8);
            cp_async16(stg + ((64 + krow0) * AST + kc * 4) * 4, kb + (size_t)krow0 * QKV_N + D_ + kc * 8);
            cp_async16(stg + ((64 + krow1) * AST + kc * 4) * 4, kb + (size_t)krow1 * QKV_N + D_ + kc * 8);
        }
        cp_commit();

        const uint32_t Kb = KVb + stage * KV_STG_WORDS * 4;
        const uint32_t Vb = Kb + 64 * AST * 4;

        float s[8][4];
        #pragma unroll
        for (int nt = 0; nt < 8; nt++)
            #pragma unroll
            for (int r = 0; r < 4; r++) s[nt][r] = 0.0f;

        #pragma unroll
        for (int ks = 0; ks < 4; ks++) {
            const int kb = ks * 8;
            uint32_t a[4];
            ldsm_x4(a, Qb + ((R + a_lr) * AST + kb + a_lk) * 4);
            #pragma unroll
            for (int p = 0; p < 4; p++) {
                uint32_t bb[4];
                ldsm_x4(bb, Kb + ((p * 16 + b_lr) * AST + kb + b_lk) * 4);
                mma_f16(s[2 * p],     a, &bb[0]);
                mma_f16(s[2 * p + 1], a, &bb[2]);
            }
        }

        float mx1 = -1e30f, mx2 = -1e30f;
        #pragma unroll
        for (int nt = 0; nt < 8; nt++) {
            mx1 = fmaxf(mx1, fmaxf(s[nt][0], s[nt][1]));
            mx2 = fmaxf(mx2, fmaxf(s[nt][2], s[nt][3]));
        }
        mx1 = fmaxf(mx1, __shfl_xor_sync(0xffffffffu, mx1, 1));
        mx1 = fmaxf(mx1, __shfl_xor_sync(0xffffffffu, mx1, 2));
        mx2 = fmaxf(mx2, __shfl_xor_sync(0xffffffffu, mx2, 1));
        mx2 = fmaxf(mx2, __shfl_xor_sync(0xffffffffu, mx2, 2));

        float mn1 = fmaxf(m1, mx1);
        float mn2 = fmaxf(m2, mx2);
        float c1 = exp2f(m1 - mn1);
        float c2 = exp2f(m2 - mn2);
        m1 = mn1; m2 = mn2;

        float rs1 = 0.0f, rs2 = 0.0f;
        #pragma unroll
        for (int nt = 0; nt < 8; nt++) {
            s[nt][0] = exp2_poly(s[nt][0] - mn1);
            s[nt][1] = exp2_poly(s[nt][1] - mn1);
            s[nt][2] = exp2_poly(s[nt][2] - mn2);
            s[nt][3] = exp2_poly(s[nt][3] - mn2);
            rs1 += s[nt][0] + s[nt][1];
            rs2 += s[nt][2] + s[nt][3];
        }
        rs1 += __shfl_xor_sync(0xffffffffu, rs1, 1);
        rs1 += __shfl_xor_sync(0xffffffffu, rs1, 2);
        rs2 += __shfl_xor_sync(0xffffffffu, rs2, 1);
        rs2 += __shfl_xor_sync(0xffffffffu, rs2, 2);
        l1 = l1 * c1 + rs1;
        l2 = l2 * c2 + rs2;

        #pragma unroll
        for (int nt = 0; nt < 8; nt++) {
            o[nt][0] *= c1; o[nt][1] *= c1;
            o[nt][2] *= c2; o[nt][3] *= c2;
        }

        #pragma unroll
        for (int nt = 0; nt < 8; nt++) {
            __half2 p0 = __floats2half2_rn(s[nt][0], s[nt][1]);
            __half2 p1 = __floats2half2_rn(s[nt][2], s[nt][3]);
            Ps[(R + qr) * AST + nt * 4 + qc]     = *(uint32_t*)&p0;
            Ps[(R + qr + 8) * AST + nt * 4 + qc] = *(uint32_t*)&p1;
        }
        __syncwarp();

        #pragma unroll
        for (int ks = 0; ks < 4; ks++) {
            const int kb = ks * 8;
            uint32_t a[4];
            ldsm_x4(a, Pb + ((R + a_lr) * AST + kb + a_lk) * 4);
            #pragma unroll
            for (int p = 0; p < 4; p++) {
                uint32_t bb[4];
                ldsm_x4_trans(bb, Vb + ((ks * 16 + v_lk) * AST + p * 8 + v_ld) * 4);
                mma_f16(o[2 * p],     a, &bb[0]);
                mma_f16(o[2 * p + 1], a, &bb[2]);
            }
        }
        __syncwarp();

        if (++stage == 3) stage = 0;
    }

    float i1 = 1.0f / l1;
    float i2 = 1.0f / l2;
    __half* ob = out + (size_t)(b * S_ + qt * 128) * D_ + h * HD_;
    #pragma unroll
    for (int nt = 0; nt < 8; nt++) {
        int col = nt * 8 + 2 * qc;
        __half2 w0 = __floats2half2_rn(o[nt][0] * i1, o[nt][1] * i1);
        __half2 w1 = __floats2half2_rn(o[nt][2] * i2, o[nt][3] * i2);
        *(__half2*)(ob + (size_t)(R + qr) * D_ + col)     = w0;
        *(__half2*)(ob + (size_t)(R + qr + 8) * D_ + col) = w1;
    }
}

// ---------------------------------------------------------------------------
// Launch
// ---------------------------------------------------------------------------
extern "C" void kernel_launch(void* const* d_in, const int* in_sizes, int n_in,
                              void* d_out, int out_size)
{
    const float* x      = (const float*)d_in[0];
    const float* qkv_w  = (const float*)d_in[1];
    const float* qkv_b  = (const float*)d_in[2];
    const float* proj_w = (const float*)d_in[3];
    const float* proj_b = (const float*)d_in[4];
    float* out = (float*)d_out;

    void *qkvh_p, *attnh_p, *xh_p, *qkvwh_p, *projwh_p;
    cudaGetSymbolAddress(&qkvh_p, g_qkvh);
    cudaGetSymbolAddress(&attnh_p, g_attnh);
    cudaGetSymbolAddress(&xh_p, g_xh);
    cudaGetSymbolAddress(&qkvwh_p, g_qkvwh);
    cudaGetSymbolAddress(&projwh_p, g_projwh);
    __half* qkvh_s   = (__half*)qkvh_p;
    __half* attnh_s  = (__half*)attnh_p;
    __half* xh_s     = (__half*)xh_p;
    __half* qkvwh_s  = (__half*)qkvwh_p;
    __half* projwh_s = (__half*)projwh_p;

    cudaFuncSetAttribute(gemm_f16_kernel<true>,
                         cudaFuncAttributeMaxDynamicSharedMemorySize,
                         GEMM_SMEM_BYTES);
    cudaFuncSetAttribute(gemm_f16_kernel<false>,
                         cudaFuncAttributeMaxDynamicSharedMemorySize,
                         GEMM_SMEM_BYTES);
    cudaFuncSetAttribute(attn_f16_kernel,
                         cudaFuncAttributeMaxDynamicSharedMemorySize,
                         AT_BYTES);

    // 0) Pre-convert inputs to fp16 (rn)
    cvt_f16_kernel<<<1024, 256>>>(x, xh_s, M_TOT * D_ / 8);
    cvt_f16_kernel<<<512, 256>>>(qkv_w, qkvwh_s, QKV_N * D_ / 8);
    cvt_f16_kernel<<<256, 256>>>(proj_w, projwh_s, D_ * D_ / 8);

    // 1) QKV projection -> fp16 qkv (q cols pre-scaled by QSC)
    gemm_f16_kernel<true><<<dim3(QKV_N / BN, M_TOT / BM), 256, GEMM_SMEM_BYTES>>>(
        xh_s, qkvwh_s, qkv_b, qkvh_s, M_TOT, QKV_N, D_);

    // 2) Flash attention (128-row Q tiles, cp.async K/V ring, 2 CTAs/SM)
    attn_f16_kernel<<<B_ * H_ * (S_ / 128), 256, AT_BYTES>>>(qkvh_s, attnh_s);

    // 3) Output projection -> f32 out
    gemm_f16_kernel<false><<<dim3(D_ / BN, M_TOT / BM), 256, GEMM_SMEM_BYTES>>>(
        attnh_s, projwh_s, proj_b, out, M_TOT, D_, D_);
}